// round 1
// baseline (speedup 1.0000x reference)
#include <cuda_runtime.h>
#include <math.h>

#define NSIDE 512
#define NPIX  (512*512)
#define NF    257

// ---- scratch (module-load allocations, allowed) ----
__device__ float2 g_tmp[NF * NPIX];   // after row IFFT pass, [f][y][x] complex
__device__ float  g_m[NF * NPIX];     // modulus fields     , [f][y][x]
__device__ float  g_accA[16 * 153];   // per j-group: E2[16], Ea[16], C1 pairs[120], (slot152: sum a^2, j==0 only)
__device__ float  g_accB[16 * 120];   // per k-group: C2 pairs[120]
__device__ float2 g_tw[256];          // exp(+2*pi*i*t/512), t=0..255 (inverse FFT twiddles)

// ---- init: twiddles + zero accumulators ----
__global__ void init_kernel() {
  int t = threadIdx.x;
  if (t < 256) {
    float s, c;
    sincospif((float)t * (1.0f / 256.0f), &s, &c); // angle = pi*t/256 = 2*pi*t/512
    g_tw[t] = make_float2(c, s);                   // +i convention (inverse DFT)
  }
  for (int i = t; i < 16 * 153; i += 256) g_accA[i] = 0.f;
  for (int i = t; i < 16 * 120; i += 256) g_accB[i] = 0.f;
}

// ---- stage 1: complex product + 512-pt inverse DIF FFT along x (bitrev-out, no reorder) ----
__global__ void rows_kernel(const float* __restrict__ xhat,
                            const float* __restrict__ pre,
                            const float* __restrict__ pim) {
  __shared__ float2 s[512];
  const int y = blockIdx.x;
  const int f = blockIdx.y;
  const int t = threadIdx.x;
  const size_t rowbase = (size_t)y * NSIDE;
  const size_t fb = (size_t)f * NPIX + rowbase;

#pragma unroll
  for (int e = 0; e < 2; e++) {
    int x = t + e * 256;
    float xr = xhat[(rowbase + x) * 2 + 0];
    float xi = xhat[(rowbase + x) * 2 + 1];
    float a = pre[fb + x];
    float b = pim[fb + x];
    s[x] = make_float2(xr * a - xi * b, xr * b + xi * a);
  }
  __syncthreads();

#pragma unroll
  for (int st = 0; st < 9; st++) {
    int half = 256 >> st;
    int k = t & (half - 1);
    int i0 = ((t & ~(half - 1)) << 1) + k;
    int i1 = i0 + half;
    float2 u = s[i0], v = s[i1];
    float2 w = g_tw[k << st];
    float dx = u.x - v.x, dy = u.y - v.y;
    s[i0] = make_float2(u.x + v.x, u.y + v.y);
    s[i1] = make_float2(dx * w.x - dy * w.y, dx * w.y + dy * w.x);
    __syncthreads();
  }

#pragma unroll
  for (int e = 0; e < 2; e++) {
    int x = t + e * 256;
    g_tmp[fb + x] = s[x];
  }
}

// ---- stage 2: 512-pt inverse DIF FFT along y (8 columns per block) + modulus ----
__global__ void cols_kernel() {
  __shared__ float2 s[512][9];  // pad 8->9 to break smem bank regularity
  const int f = blockIdx.y;
  const int x0 = blockIdx.x * 8;
  const int t = threadIdx.x;
  const size_t fb = (size_t)f * NPIX;

  for (int i = t; i < 4096; i += 256) {
    int y = i >> 3, c = i & 7;
    s[y][c] = g_tmp[fb + (size_t)y * NSIDE + x0 + c];
  }
  __syncthreads();

#pragma unroll
  for (int st = 0; st < 9; st++) {
    int half = 256 >> st;
#pragma unroll
    for (int it = 0; it < 8; it++) {
      int idx = it * 256 + t;
      int c = idx & 7, u = idx >> 3;
      int k = u & (half - 1);
      int i0 = ((u & ~(half - 1)) << 1) + k;
      int i1 = i0 + half;
      float2 a = s[i0][c], b = s[i1][c];
      float2 w = g_tw[k << st];
      float dx = a.x - b.x, dy = a.y - b.y;
      s[i0][c] = make_float2(a.x + b.x, a.y + b.y);
      s[i1][c] = make_float2(dx * w.x - dy * w.y, dx * w.y + dy * w.x);
    }
    __syncthreads();
  }

  const float inv = 1.0f / (float)NPIX;  // 1/N^2 ifft2 scaling, applied BEFORE +1e-8
  for (int i = t; i < 4096; i += 256) {
    int y = i >> 3, c = i & 7;
    float2 v = s[y][c];
    float re = v.x * inv, im = v.y * inv;
    g_m[fb + (size_t)y * NSIDE + x0 + c] = sqrtf(re * re + im * im + 1e-8f);
  }
}

// ---- stage 3a: per-j group (16 orientations + lowpass): E2, Ea, C1 pairs, a^2 ----
__global__ void __launch_bounds__(256) gramA_kernel() {
  const int j = blockIdx.y;
  const int t = threadIdx.x;
  const int base = blockIdx.x * 4096 + t;
  float acc[153];
#pragma unroll
  for (int i = 0; i < 153; i++) acc[i] = 0.f;
  const float* __restrict__ mp = g_m + NPIX;  // filters 1..256

#pragma unroll 1
  for (int it = 0; it < 16; it++) {
    int pix = base + it * 256;
    float a = g_m[pix];
    float v[16];
#pragma unroll
    for (int k = 0; k < 16; k++)
      v[k] = mp[(size_t)(k * 16 + j) * NPIX + pix];
    if (j == 0) acc[152] += a * a;
#pragma unroll
    for (int k = 0; k < 16; k++) {
      acc[k]      += v[k] * v[k];
      acc[16 + k] += v[k] * a;
    }
    int c = 32;
#pragma unroll
    for (int k = 0; k < 16; k++)
#pragma unroll
      for (int l = k + 1; l < 16; l++)
        acc[c++] += v[k] * v[l];
  }

  __shared__ float ws[8][153];
  int lane = t & 31, wp = t >> 5;
#pragma unroll
  for (int i = 0; i < 153; i++) {
    float x = acc[i];
    x += __shfl_down_sync(0xffffffffu, x, 16);
    x += __shfl_down_sync(0xffffffffu, x, 8);
    x += __shfl_down_sync(0xffffffffu, x, 4);
    x += __shfl_down_sync(0xffffffffu, x, 2);
    x += __shfl_down_sync(0xffffffffu, x, 1);
    if (lane == 0) ws[wp][i] = x;
  }
  __syncthreads();
  if (t < 153) {
    float sum = 0.f;
#pragma unroll
    for (int w2 = 0; w2 < 8; w2++) sum += ws[w2][t];
    atomicAdd(&g_accA[j * 153 + t], sum);
  }
}

// ---- stage 3b: per-k group (16 scales): C2 pairs ----
__global__ void __launch_bounds__(256) gramB_kernel() {
  const int k = blockIdx.y;
  const int t = threadIdx.x;
  const int base = blockIdx.x * 4096 + t;
  float acc[120];
#pragma unroll
  for (int i = 0; i < 120; i++) acc[i] = 0.f;
  const float* __restrict__ mp = g_m + NPIX;

#pragma unroll 1
  for (int it = 0; it < 16; it++) {
    int pix = base + it * 256;
    float v[16];
#pragma unroll
    for (int j = 0; j < 16; j++)
      v[j] = mp[(size_t)(k * 16 + j) * NPIX + pix];
    int c = 0;
#pragma unroll
    for (int j = 0; j < 16; j++)
#pragma unroll
      for (int l = j + 1; l < 16; l++)
        acc[c++] += v[j] * v[l];
  }

  __shared__ float ws[8][120];
  int lane = t & 31, wp = t >> 5;
#pragma unroll
  for (int i = 0; i < 120; i++) {
    float x = acc[i];
    x += __shfl_down_sync(0xffffffffu, x, 16);
    x += __shfl_down_sync(0xffffffffu, x, 8);
    x += __shfl_down_sync(0xffffffffu, x, 4);
    x += __shfl_down_sync(0xffffffffu, x, 2);
    x += __shfl_down_sync(0xffffffffu, x, 1);
    if (lane == 0) ws[wp][i] = x;
  }
  __syncthreads();
  if (t < 120) {
    float sum = 0.f;
#pragma unroll
    for (int w2 = 0; w2 < 8; w2++) sum += ws[w2][t];
    atomicAdd(&g_accB[k * 120 + t], sum);
  }
}

// ---- stage 4: assemble into the reference's exact loop ordering ----
__global__ void assemble_kernel(float* __restrict__ out) {
  const int t = threadIdx.x;
  const float inv = 1.0f / (float)NPIX;
  if (t == 0) out[0] = g_accA[152] * inv;  // s0 = mean(a^2)
  if (t >= 256) return;
  int i = t >> 4, j = t & 15;  // i = orientation k, j = scale
  int rowsum = 152 * i + 16 * (15 * i - (i * (i - 1)) / 2);
  int segsum = 2 * j + ((i < 15) ? (15 - i) * j : 0) + 15 * j - (j * (j - 1)) / 2;
  int pos = 1 + rowsum + segsum;
  out[pos++] = g_accA[j * 153 + i] * inv;        // E2[i,j]
  out[pos++] = g_accA[j * 153 + 16 + i] * inv;   // Ea[i,j]
  if (i < 15)
    for (int l = i + 1; l < 16; l++)             // C1[i, l, j]
      out[pos++] = g_accA[j * 153 + 32 + (15 * i - (i * (i - 1)) / 2 + (l - i - 1))] * inv;
  if (j < 15)
    for (int l = j + 1; l < 16; l++)             // C2[i, j, l]
      out[pos++] = g_accB[i * 120 + (15 * j - (j * (j - 1)) / 2 + (l - j - 1))] * inv;
}

extern "C" void kernel_launch(void* const* d_in, const int* in_sizes, int n_in,
                              void* d_out, int out_size) {
  const float* xhat = (const float*)d_in[0];   // [512,512,2]
  const float* pre  = (const float*)d_in[1];   // [257,512,512]
  const float* pim  = (const float*)d_in[2];   // [257,512,512]
  float* out = (float*)d_out;                  // [4353]

  init_kernel<<<1, 256>>>();
  rows_kernel<<<dim3(NSIDE, NF), 256>>>(xhat, pre, pim);
  cols_kernel<<<dim3(NSIDE / 8, NF), 256>>>();
  gramA_kernel<<<dim3(64, 16), 256>>>();
  gramB_kernel<<<dim3(64, 16), 256>>>();
  assemble_kernel<<<1, 256>>>(out);
}

// round 2
// speedup vs baseline: 2.2670x; 2.2670x over previous
#include <cuda_runtime.h>
#include <math.h>

#define NSIDE 512
#define NPIX  (512*512)
#define NF    257

// ---- scratch ----
__device__ __align__(16) float2 g_tmp[NF * NPIX];  // after row pass, layout [f][x][y]
__device__ __align__(16) float  g_m[NF * NPIX];    // modulus, layout [f][x][y] (permutation-consistent)
__device__ float  g_accA[16 * 153];
__device__ float  g_accB[16 * 120];
__device__ float2 g_tw512[512];                    // exp(+2*pi*i*m/512)

// ---- complex helpers ----
__device__ __forceinline__ float2 cadd(float2 a, float2 b){ return make_float2(a.x+b.x, a.y+b.y); }
__device__ __forceinline__ float2 csub(float2 a, float2 b){ return make_float2(a.x-b.x, a.y-b.y); }
__device__ __forceinline__ float2 cmuli(float2 a){ return make_float2(-a.y, a.x); }  // * i
__device__ __forceinline__ float2 cmul(float2 a, float2 b){
  return make_float2(a.x*b.x - a.y*b.y, a.x*b.y + a.y*b.x);
}

// 8-point DFT, positive (inverse) sign, natural-order in/out
__device__ __forceinline__ void fft8(float2 v[8]) {
  const float C = 0.70710678118654752440f;
  // FFT4 over evens (v0,v2,v4,v6)
  float2 es0 = cadd(v[0], v[4]), ed0 = csub(v[0], v[4]);
  float2 es1 = cadd(v[2], v[6]), ed1 = csub(v[2], v[6]);
  float2 E0 = cadd(es0, es1);
  float2 E1 = cadd(ed0, cmuli(ed1));
  float2 E2 = csub(es0, es1);
  float2 E3 = csub(ed0, cmuli(ed1));
  // FFT4 over odds (v1,v3,v5,v7)
  float2 os0 = cadd(v[1], v[5]), od0 = csub(v[1], v[5]);
  float2 os1 = cadd(v[3], v[7]), od1 = csub(v[3], v[7]);
  float2 O0 = cadd(os0, os1);
  float2 O1 = cadd(od0, cmuli(od1));
  float2 O2 = csub(os0, os1);
  float2 O3 = csub(od0, cmuli(od1));
  // twiddle odds by w8^k
  float2 O1t = make_float2(C*(O1.x - O1.y), C*(O1.x + O1.y));
  float2 O2t = cmuli(O2);
  float2 O3t = make_float2(-C*(O3.x + O3.y), C*(O3.x - O3.y));
  v[0] = cadd(E0, O0);  v[4] = csub(E0, O0);
  v[1] = cadd(E1, O1t); v[5] = csub(E1, O1t);
  v[2] = cadd(E2, O2t); v[6] = csub(E2, O2t);
  v[3] = cadd(E3, O3t); v[7] = csub(E3, O3t);
}

// 8x8 transpose among 8 lanes differing in low-3 lane bits (f3 = lane&7)
__device__ __forceinline__ void transpose8(float2 v[8], int f3) {
#pragma unroll
  for (int mb = 0; mb < 3; mb++) {
    const int m = 1 << mb;
#pragma unroll
    for (int i = 0; i < 8; i++) {
      if ((i & m) == 0) {
        const int ip = i | m;
        const bool hi = (f3 & m) != 0;
        float2 send = hi ? v[i] : v[ip];
        unsigned long long u = ((unsigned long long)__float_as_uint(send.y) << 32)
                             | (unsigned long long)__float_as_uint(send.x);
        u = __shfl_xor_sync(0xffffffffu, u, m);
        float2 got = make_float2(__uint_as_float((unsigned)u),
                                 __uint_as_float((unsigned)(u >> 32)));
        if (hi) v[i] = got; else v[ip] = got;
      }
    }
  }
}

// ---- init: twiddles + zero accumulators ----
__global__ void init_kernel() {
  int t = threadIdx.x;
  for (int m = t; m < 512; m += 256) {
    float s, c;
    sincospif((float)m * (1.0f / 256.0f), &s, &c);
    g_tw512[m] = make_float2(c, s);
  }
  for (int i = t; i < 16 * 153; i += 256) g_accA[i] = 0.f;
  for (int i = t; i < 16 * 120; i += 256) g_accB[i] = 0.f;
}

// ---- stage 1: complex product + 512-pt IFFT along x; writes TRANSPOSED [f][x][y] ----
__global__ void __launch_bounds__(256) rows_kernel(const float2* __restrict__ xh2,
                                                   const float* __restrict__ pre,
                                                   const float* __restrict__ pim) {
  __shared__ float2 S[2560];  // stage buffers: 4 rows * 576; reused as [x][row] stride 5
  const int tid = threadIdx.x;
  const int row = tid >> 6, t = tid & 63;
  const int f = blockIdx.y;
  const int y0 = blockIdx.x << 2;
  const int y = y0 + row;
  const size_t rowoff = (size_t)y * NSIDE;
  const size_t fb = (size_t)f * NPIX + rowoff;

  float2 v[8];
#pragma unroll
  for (int q = 0; q < 8; q++) {
    int x = t + (q << 6);
    float2 xc = xh2[rowoff + x];
    float pr = pre[fb + x], pq = pim[fb + x];
    v[q] = make_float2(xc.x * pr - xc.y * pq, xc.x * pq + xc.y * pr);
  }
  fft8(v);
  float2* Sr = S + row * 576;
#pragma unroll
  for (int r = 0; r < 8; r++)
    Sr[r * 72 + t] = (r == 0) ? v[0] : cmul(v[r], g_tw512[t * r]);
  __syncthreads();

  const int r = t >> 3, T = t & 7;
#pragma unroll
  for (int q = 0; q < 8; q++)
    v[q] = Sr[r * 72 + T + (q << 3)];
  fft8(v);
#pragma unroll
  for (int rp = 1; rp < 8; rp++)
    v[rp] = cmul(v[rp], g_tw512[8 * T * rp]);
  transpose8(v, T);
  fft8(v);
  __syncthreads();   // safe to reuse S

#pragma unroll
  for (int k3 = 0; k3 < 8; k3++) {
    int x = (k3 << 6) + t;
    S[x * 5 + row] = v[k3];
  }
  __syncthreads();

  const size_t fxb = (size_t)f * NPIX;
#pragma unroll
  for (int i = 0; i < 2; i++) {
    int x = tid + (i << 8);
    float2 a0 = S[x * 5 + 0], a1 = S[x * 5 + 1];
    float2 a2 = S[x * 5 + 2], a3 = S[x * 5 + 3];
    float4* dst = (float4*)(g_tmp + fxb + (size_t)x * NSIDE + y0);
    dst[0] = make_float4(a0.x, a0.y, a1.x, a1.y);
    dst[1] = make_float4(a2.x, a2.y, a3.x, a3.y);
  }
}

// ---- stage 2: 512-pt IFFT along y (contiguous in [f][x][y]) + modulus ----
__global__ void __launch_bounds__(256) cols_kernel() {
  __shared__ float2 S[4 * 576];
  const int tid = threadIdx.x;
  const int cc = tid >> 6, t = tid & 63;
  const int f = blockIdx.y;
  const int x = (blockIdx.x << 2) + cc;
  const size_t colbase = (size_t)f * NPIX + (size_t)x * NSIDE;

  float2 v[8];
#pragma unroll
  for (int q = 0; q < 8; q++)
    v[q] = g_tmp[colbase + t + (q << 6)];
  fft8(v);
  float2* Sr = S + cc * 576;
#pragma unroll
  for (int r = 0; r < 8; r++)
    Sr[r * 72 + t] = (r == 0) ? v[0] : cmul(v[r], g_tw512[t * r]);
  __syncthreads();

  const int r = t >> 3, T = t & 7;
#pragma unroll
  for (int q = 0; q < 8; q++)
    v[q] = Sr[r * 72 + T + (q << 3)];
  fft8(v);
#pragma unroll
  for (int rp = 1; rp < 8; rp++)
    v[rp] = cmul(v[rp], g_tw512[8 * T * rp]);
  transpose8(v, T);
  fft8(v);

  const float inv = 1.0f / (float)NPIX;
#pragma unroll
  for (int k3 = 0; k3 < 8; k3++) {
    float re = v[k3].x * inv, im = v[k3].y * inv;
    g_m[colbase + (k3 << 6) + t] = sqrtf(re * re + im * im + 1e-8f);
  }
}

// ---- stage 3a: per-j group: E2, Ea, C1 pairs, a^2 (float2 loads) ----
__global__ void __launch_bounds__(256) gramA_kernel() {
  const int j = blockIdx.y;
  const int t = threadIdx.x;
  const int base = blockIdx.x * 2048 + t;  // float2 index
  const float2* __restrict__ m2 = (const float2*)g_m;
  const size_t F2 = NPIX / 2;
  float acc[153];
#pragma unroll
  for (int i = 0; i < 153; i++) acc[i] = 0.f;

#pragma unroll 1
  for (int it = 0; it < 8; it++) {
    int pix = base + it * 256;
    float2 a = m2[pix];
    float2 v[16];
#pragma unroll
    for (int k = 0; k < 16; k++)
      v[k] = m2[(size_t)(1 + k * 16 + j) * F2 + pix];
    if (j == 0) acc[152] += a.x * a.x + a.y * a.y;
#pragma unroll
    for (int k = 0; k < 16; k++) {
      acc[k]      += v[k].x * v[k].x + v[k].y * v[k].y;
      acc[16 + k] += v[k].x * a.x   + v[k].y * a.y;
    }
    int c = 32;
#pragma unroll
    for (int k = 0; k < 16; k++)
#pragma unroll
      for (int l = k + 1; l < 16; l++)
        acc[c++] += v[k].x * v[l].x + v[k].y * v[l].y;
  }

  __shared__ float ws[8][153];
  int lane = t & 31, wp = t >> 5;
#pragma unroll
  for (int i = 0; i < 153; i++) {
    float x = acc[i];
    x += __shfl_down_sync(0xffffffffu, x, 16);
    x += __shfl_down_sync(0xffffffffu, x, 8);
    x += __shfl_down_sync(0xffffffffu, x, 4);
    x += __shfl_down_sync(0xffffffffu, x, 2);
    x += __shfl_down_sync(0xffffffffu, x, 1);
    if (lane == 0) ws[wp][i] = x;
  }
  __syncthreads();
  if (t < 153) {
    float sum = 0.f;
#pragma unroll
    for (int w2 = 0; w2 < 8; w2++) sum += ws[w2][t];
    atomicAdd(&g_accA[j * 153 + t], sum);
  }
}

// ---- stage 3b: per-k group: C2 pairs (float4 loads) ----
__global__ void __launch_bounds__(256) gramB_kernel() {
  const int k = blockIdx.y;
  const int t = threadIdx.x;
  const int base = blockIdx.x * 1024 + t;  // float4 index
  const float4* __restrict__ m4 = (const float4*)g_m;
  const size_t F4 = NPIX / 4;
  float acc[120];
#pragma unroll
  for (int i = 0; i < 120; i++) acc[i] = 0.f;

#pragma unroll 1
  for (int it = 0; it < 4; it++) {
    int pix = base + it * 256;
    float4 v[16];
#pragma unroll
    for (int j = 0; j < 16; j++)
      v[j] = m4[(size_t)(1 + k * 16 + j) * F4 + pix];
    int c = 0;
#pragma unroll
    for (int j = 0; j < 16; j++)
#pragma unroll
      for (int l = j + 1; l < 16; l++)
        acc[c++] += v[j].x * v[l].x + v[j].y * v[l].y
                  + v[j].z * v[l].z + v[j].w * v[l].w;
  }

  __shared__ float ws[8][120];
  int lane = t & 31, wp = t >> 5;
#pragma unroll
  for (int i = 0; i < 120; i++) {
    float x = acc[i];
    x += __shfl_down_sync(0xffffffffu, x, 16);
    x += __shfl_down_sync(0xffffffffu, x, 8);
    x += __shfl_down_sync(0xffffffffu, x, 4);
    x += __shfl_down_sync(0xffffffffu, x, 2);
    x += __shfl_down_sync(0xffffffffu, x, 1);
    if (lane == 0) ws[wp][i] = x;
  }
  __syncthreads();
  if (t < 120) {
    float sum = 0.f;
#pragma unroll
    for (int w2 = 0; w2 < 8; w2++) sum += ws[w2][t];
    atomicAdd(&g_accB[k * 120 + t], sum);
  }
}

// ---- stage 4: assemble (reference loop ordering) ----
__global__ void assemble_kernel(float* __restrict__ out) {
  const int t = threadIdx.x;
  const float inv = 1.0f / (float)NPIX;
  if (t == 0) out[0] = g_accA[152] * inv;
  if (t >= 256) return;
  int i = t >> 4, j = t & 15;
  int rowsum = 152 * i + 16 * (15 * i - (i * (i - 1)) / 2);
  int segsum = 2 * j + ((i < 15) ? (15 - i) * j : 0) + 15 * j - (j * (j - 1)) / 2;
  int pos = 1 + rowsum + segsum;
  out[pos++] = g_accA[j * 153 + i] * inv;
  out[pos++] = g_accA[j * 153 + 16 + i] * inv;
  if (i < 15)
    for (int l = i + 1; l < 16; l++)
      out[pos++] = g_accA[j * 153 + 32 + (15 * i - (i * (i - 1)) / 2 + (l - i - 1))] * inv;
  if (j < 15)
    for (int l = j + 1; l < 16; l++)
      out[pos++] = g_accB[i * 120 + (15 * j - (j * (j - 1)) / 2 + (l - j - 1))] * inv;
}

extern "C" void kernel_launch(void* const* d_in, const int* in_sizes, int n_in,
                              void* d_out, int out_size) {
  const float2* xh2 = (const float2*)d_in[0];
  const float* pre  = (const float*)d_in[1];
  const float* pim  = (const float*)d_in[2];
  float* out = (float*)d_out;

  init_kernel<<<1, 256>>>();
  rows_kernel<<<dim3(NSIDE / 4, NF), 256>>>(xh2, pre, pim);
  cols_kernel<<<dim3(NSIDE / 4, NF), 256>>>();
  gramA_kernel<<<dim3(64, 16), 256>>>();
  gramB_kernel<<<dim3(64, 16), 256>>>();
  assemble_kernel<<<1, 256>>>(out);
}

// round 3
// speedup vs baseline: 2.5476x; 1.1238x over previous
#include <cuda_runtime.h>
#include <cuda_fp16.h>
#include <math.h>

#define NSIDE 512
#define NPIX  (512*512)
#define NF    257

// ---- scratch ----
__device__ __align__(16) __half2 g_tmp[NF * NPIX];  // row-pass output, layout [f][x][y], complex fp16
__device__ __align__(16) __half  g_m[NF * NPIX];    // modulus * 512, layout [f][x][y], fp16
__device__ float  g_accA[16 * 153];
__device__ float  g_accB[16 * 120];
__device__ float2 g_tw512[512];                     // exp(+2*pi*i*m/512)

// ---- complex helpers ----
__device__ __forceinline__ float2 cadd(float2 a, float2 b){ return make_float2(a.x+b.x, a.y+b.y); }
__device__ __forceinline__ float2 csub(float2 a, float2 b){ return make_float2(a.x-b.x, a.y-b.y); }
__device__ __forceinline__ float2 cmuli(float2 a){ return make_float2(-a.y, a.x); }
__device__ __forceinline__ float2 cmul(float2 a, float2 b){
  return make_float2(a.x*b.x - a.y*b.y, a.x*b.y + a.y*b.x);
}
__device__ __forceinline__ unsigned pack_h2(float2 a){
  __half2 h = __floats2half2_rn(a.x, a.y);
  return *reinterpret_cast<unsigned*>(&h);
}

// 8-point DFT, +i sign, natural order
__device__ __forceinline__ void fft8(float2 v[8]) {
  const float C = 0.70710678118654752440f;
  float2 es0 = cadd(v[0], v[4]), ed0 = csub(v[0], v[4]);
  float2 es1 = cadd(v[2], v[6]), ed1 = csub(v[2], v[6]);
  float2 E0 = cadd(es0, es1);
  float2 E1 = cadd(ed0, cmuli(ed1));
  float2 E2 = csub(es0, es1);
  float2 E3 = csub(ed0, cmuli(ed1));
  float2 os0 = cadd(v[1], v[5]), od0 = csub(v[1], v[5]);
  float2 os1 = cadd(v[3], v[7]), od1 = csub(v[3], v[7]);
  float2 O0 = cadd(os0, os1);
  float2 O1 = cadd(od0, cmuli(od1));
  float2 O2 = csub(os0, os1);
  float2 O3 = csub(od0, cmuli(od1));
  float2 O1t = make_float2(C*(O1.x - O1.y), C*(O1.x + O1.y));
  float2 O2t = cmuli(O2);
  float2 O3t = make_float2(-C*(O3.x + O3.y), C*(O3.x - O3.y));
  v[0] = cadd(E0, O0);  v[4] = csub(E0, O0);
  v[1] = cadd(E1, O1t); v[5] = csub(E1, O1t);
  v[2] = cadd(E2, O2t); v[6] = csub(E2, O2t);
  v[3] = cadd(E3, O3t); v[7] = csub(E3, O3t);
}

// 8x8 transpose among 8 lanes differing in low-3 lane bits
__device__ __forceinline__ void transpose8(float2 v[8], int f3) {
#pragma unroll
  for (int mb = 0; mb < 3; mb++) {
    const int m = 1 << mb;
#pragma unroll
    for (int i = 0; i < 8; i++) {
      if ((i & m) == 0) {
        const int ip = i | m;
        const bool hi = (f3 & m) != 0;
        float2 send = hi ? v[i] : v[ip];
        unsigned long long u = ((unsigned long long)__float_as_uint(send.y) << 32)
                             | (unsigned long long)__float_as_uint(send.x);
        u = __shfl_xor_sync(0xffffffffu, u, m);
        float2 got = make_float2(__uint_as_float((unsigned)u),
                                 __uint_as_float((unsigned)(u >> 32)));
        if (hi) v[i] = got; else v[ip] = got;
      }
    }
  }
}

__global__ void init_kernel() {
  int t = threadIdx.x;
  for (int m = t; m < 512; m += 256) {
    float s, c;
    sincospif((float)m * (1.0f / 256.0f), &s, &c);
    g_tw512[m] = make_float2(c, s);
  }
  for (int i = t; i < 16 * 153; i += 256) g_accA[i] = 0.f;
  for (int i = t; i < 16 * 120; i += 256) g_accB[i] = 0.f;
}

// ---- stage 1: product + 512-pt IFFT along x; transposed fp16 store [f][x][y] ----
// 8 rows per block, 512 threads (64 per row).
__global__ void __launch_bounds__(512) rows_kernel(const float2* __restrict__ xh2,
                                                   const float* __restrict__ pre,
                                                   const float* __restrict__ pim) {
  __shared__ float2 S[5120];  // FFT stage: 8 rows * 576 ; store stage: [x]*10+[row]
  const int tid = threadIdx.x;
  const int row = tid >> 6, t = tid & 63;
  const int f = blockIdx.y;
  const int y0 = blockIdx.x << 3;
  const int y = y0 + row;
  const size_t rowoff = (size_t)y * NSIDE;
  const size_t fb = (size_t)f * NPIX + rowoff;

  float2 v[8];
#pragma unroll
  for (int q = 0; q < 8; q++) {
    int x = t + (q << 6);
    float2 xc = xh2[rowoff + x];
    float pr = __ldcs(pre + fb + x), pq = __ldcs(pim + fb + x);
    v[q] = make_float2(xc.x * pr - xc.y * pq, xc.x * pq + xc.y * pr);
  }
  fft8(v);
  float2* Sr = S + row * 576;
#pragma unroll
  for (int r = 0; r < 8; r++)
    Sr[r * 72 + t] = (r == 0) ? v[0] : cmul(v[r], g_tw512[t * r]);
  __syncthreads();

  const int r = t >> 3, T = t & 7;
#pragma unroll
  for (int q = 0; q < 8; q++)
    v[q] = Sr[r * 72 + T + (q << 3)];
  fft8(v);
#pragma unroll
  for (int rp = 1; rp < 8; rp++)
    v[rp] = cmul(v[rp], g_tw512[8 * T * rp]);
  transpose8(v, T);
  fft8(v);
  __syncthreads();   // S reusable

#pragma unroll
  for (int k3 = 0; k3 < 8; k3++) {
    int x = (k3 << 6) + t;
    S[x * 10 + row] = v[k3];
  }
  __syncthreads();

  const size_t fxb = (size_t)f * NPIX;
  {
    int x = tid;
    float2 b[8];
#pragma unroll
    for (int rr = 0; rr < 8; rr++) b[rr] = S[x * 10 + rr];
    uint4 lo = make_uint4(pack_h2(b[0]), pack_h2(b[1]), pack_h2(b[2]), pack_h2(b[3]));
    uint4 hi = make_uint4(pack_h2(b[4]), pack_h2(b[5]), pack_h2(b[6]), pack_h2(b[7]));
    uint4* dst = reinterpret_cast<uint4*>(g_tmp + fxb + (size_t)x * NSIDE + y0);
    dst[0] = lo; dst[1] = hi;
  }
}

// ---- stage 2: 512-pt IFFT along y (contiguous) + scaled modulus (fp16) ----
__global__ void __launch_bounds__(256) cols_kernel() {
  __shared__ float2 S[4 * 576];
  const int tid = threadIdx.x;
  const int cc = tid >> 6, t = tid & 63;
  const int f = blockIdx.y;
  const int x = (blockIdx.x << 2) + cc;
  const size_t colbase = (size_t)f * NPIX + (size_t)x * NSIDE;

  float2 v[8];
#pragma unroll
  for (int q = 0; q < 8; q++)
    v[q] = __half22float2(g_tmp[colbase + t + (q << 6)]);
  fft8(v);
  float2* Sr = S + cc * 576;
#pragma unroll
  for (int r = 0; r < 8; r++)
    Sr[r * 72 + t] = (r == 0) ? v[0] : cmul(v[r], g_tw512[t * r]);
  __syncthreads();

  const int r = t >> 3, T = t & 7;
#pragma unroll
  for (int q = 0; q < 8; q++)
    v[q] = Sr[r * 72 + T + (q << 3)];
  fft8(v);
#pragma unroll
  for (int rp = 1; rp < 8; rp++)
    v[rp] = cmul(v[rp], g_tw512[8 * T * rp]);
  transpose8(v, T);
  fft8(v);

  const float inv = 1.0f / (float)NPIX;
#pragma unroll
  for (int k3 = 0; k3 < 8; k3++) {
    float re = v[k3].x * inv, im = v[k3].y * inv;
    float m = sqrtf(re * re + im * im + 1e-8f);
    g_m[colbase + (k3 << 6) + t] = __float2half_rn(m * 512.0f);
  }
}

// ---- stage 3a: per-j group, acc-split in two parts ----
// slot layout per j: [0..15]=E2, [16..31]=Ea, [32..151]=C1 pairs c=0..119, [152]=a^2(j==0)
template<int PART>
__global__ void __launch_bounds__(128) gramA_kernel() {
  const int j = blockIdx.y;
  const int t = threadIdx.x;
  const int base = blockIdx.x * 1024 + t;   // half2 index; 8 iters * 128 threads
  const __half2* __restrict__ m2 = (const __half2*)g_m;
  const size_t F2 = NPIX / 2;
  constexpr int NACC = (PART == 0) ? 93 : 60;
  float acc[NACC];
#pragma unroll
  for (int i = 0; i < NACC; i++) acc[i] = 0.f;

#pragma unroll 1
  for (int it = 0; it < 8; it++) {
    int pix = base + it * 128;
    float2 v[16];
#pragma unroll
    for (int k = 0; k < 16; k++)
      v[k] = __half22float2(m2[(size_t)(1 + k * 16 + j) * F2 + pix]);
    if (PART == 0) {
      float2 a = __half22float2(m2[pix]);
      acc[92] += a.x * a.x + a.y * a.y;
#pragma unroll
      for (int k = 0; k < 16; k++) {
        acc[k]      += v[k].x * v[k].x + v[k].y * v[k].y;
        acc[16 + k] += v[k].x * a.x + v[k].y * a.y;
      }
    }
    int c = 0;
#pragma unroll
    for (int k = 0; k < 16; k++)
#pragma unroll
      for (int l = k + 1; l < 16; l++) {
        if (PART == 0 ? (c < 60) : (c >= 60)) {
          int ai = (PART == 0) ? (32 + c) : (c - 60);
          acc[ai] += v[k].x * v[l].x + v[k].y * v[l].y;
        }
        c++;
      }
  }

  __shared__ float ws[4][NACC];
  int lane = t & 31, wp = t >> 5;
#pragma unroll
  for (int i = 0; i < NACC; i++) {
    float x = acc[i];
    x += __shfl_down_sync(0xffffffffu, x, 16);
    x += __shfl_down_sync(0xffffffffu, x, 8);
    x += __shfl_down_sync(0xffffffffu, x, 4);
    x += __shfl_down_sync(0xffffffffu, x, 2);
    x += __shfl_down_sync(0xffffffffu, x, 1);
    if (lane == 0) ws[wp][i] = x;
  }
  __syncthreads();
  if (t < NACC) {
    float s = ws[0][t] + ws[1][t] + ws[2][t] + ws[3][t];
    if (PART == 0) {
      if (t < 92) atomicAdd(&g_accA[j * 153 + t], s);
      else if (j == 0) atomicAdd(&g_accA[152], s);
    } else {
      atomicAdd(&g_accA[j * 153 + 92 + t], s);
    }
  }
}

// ---- stage 3b: per-k group, acc-split in two parts (pairs c in [PART*60, PART*60+60)) ----
template<int PART>
__global__ void __launch_bounds__(128) gramB_kernel() {
  const int k = blockIdx.y;
  const int t = threadIdx.x;
  const int base = blockIdx.x * 1024 + t;
  const __half2* __restrict__ m2 = (const __half2*)g_m;
  const size_t F2 = NPIX / 2;
  float acc[60];
#pragma unroll
  for (int i = 0; i < 60; i++) acc[i] = 0.f;

#pragma unroll 1
  for (int it = 0; it < 8; it++) {
    int pix = base + it * 128;
    float2 v[16];
#pragma unroll
    for (int jj = 0; jj < 16; jj++)
      v[jj] = __half22float2(m2[(size_t)(1 + k * 16 + jj) * F2 + pix]);
    int c = 0;
#pragma unroll
    for (int jj = 0; jj < 16; jj++)
#pragma unroll
      for (int l = jj + 1; l < 16; l++) {
        if (c >= PART * 60 && c < PART * 60 + 60)
          acc[c - PART * 60] += v[jj].x * v[l].x + v[jj].y * v[l].y;
        c++;
      }
  }

  __shared__ float ws[4][60];
  int lane = t & 31, wp = t >> 5;
#pragma unroll
  for (int i = 0; i < 60; i++) {
    float x = acc[i];
    x += __shfl_down_sync(0xffffffffu, x, 16);
    x += __shfl_down_sync(0xffffffffu, x, 8);
    x += __shfl_down_sync(0xffffffffu, x, 4);
    x += __shfl_down_sync(0xffffffffu, x, 2);
    x += __shfl_down_sync(0xffffffffu, x, 1);
    if (lane == 0) ws[wp][i] = x;
  }
  __syncthreads();
  if (t < 60) {
    float s = ws[0][t] + ws[1][t] + ws[2][t] + ws[3][t];
    atomicAdd(&g_accB[k * 120 + PART * 60 + t], s);
  }
}

// ---- stage 4: assemble (reference ordering); descale fp16's x512 and /NPIX ----
__global__ void assemble_kernel(float* __restrict__ out) {
  const int t = threadIdx.x;
  const float inv = 1.0f / ((float)NPIX * 262144.0f);  // 1/NPIX (mean) * 1/512^2 (descale)
  if (t == 0) out[0] = g_accA[152] * inv;
  if (t >= 256) return;
  int i = t >> 4, j = t & 15;
  int rowsum = 152 * i + 16 * (15 * i - (i * (i - 1)) / 2);
  int segsum = 2 * j + ((i < 15) ? (15 - i) * j : 0) + 15 * j - (j * (j - 1)) / 2;
  int pos = 1 + rowsum + segsum;
  out[pos++] = g_accA[j * 153 + i] * inv;
  out[pos++] = g_accA[j * 153 + 16 + i] * inv;
  if (i < 15)
    for (int l = i + 1; l < 16; l++)
      out[pos++] = g_accA[j * 153 + 32 + (15 * i - (i * (i - 1)) / 2 + (l - i - 1))] * inv;
  if (j < 15)
    for (int l = j + 1; l < 16; l++)
      out[pos++] = g_accB[i * 120 + (15 * j - (j * (j - 1)) / 2 + (l - j - 1))] * inv;
}

extern "C" void kernel_launch(void* const* d_in, const int* in_sizes, int n_in,
                              void* d_out, int out_size) {
  const float2* xh2 = (const float2*)d_in[0];
  const float* pre  = (const float*)d_in[1];
  const float* pim  = (const float*)d_in[2];
  float* out = (float*)d_out;

  init_kernel<<<1, 256>>>();
  rows_kernel<<<dim3(NSIDE / 8, NF), 512>>>(xh2, pre, pim);
  cols_kernel<<<dim3(NSIDE / 4, NF), 256>>>();
  gramA_kernel<0><<<dim3(128, 16), 128>>>();
  gramA_kernel<1><<<dim3(128, 16), 128>>>();
  gramB_kernel<0><<<dim3(128, 16), 128>>>();
  gramB_kernel<1><<<dim3(128, 16), 128>>>();
  assemble_kernel<<<1, 256>>>(out);
}